// round 4
// baseline (speedup 1.0000x reference)
#include <cuda_runtime.h>

#define B 512
#define T 512
#define H 128
#define G4 (4 * H)  // 512

// ---------------- device state (allocation-free scratch) ----------------
// w1e stored TRANSPOSED: [b][h][t']  -> coalesced loads in the hot loop
__device__ float g_w1eT[(size_t)B * H * T];

// ---------------- tanh exactly as XLA lowers jnp.tanh (f32) ----------------
__device__ __forceinline__ float tanh_xla(float x) {
    float xc = fminf(fmaxf(x, -9.0f), 9.0f);
    float x2 = xc * xc;
    float p = fmaf(x2, -2.76076847742355e-16f, 2.00018790482477e-13f);
    p = fmaf(x2, p, -8.60467152213735e-11f);
    p = fmaf(x2, p, 5.12229709037114e-08f);
    p = fmaf(x2, p, 1.48572235717979e-05f);
    p = fmaf(x2, p, 6.37261928875436e-04f);
    p = fmaf(x2, p, 4.89352455891786e-03f);
    p = xc * p;
    float q = fmaf(x2, 1.19825839466702e-06f, 1.18534705686654e-04f);
    q = fmaf(x2, q, 2.26843463243900e-03f);
    q = fmaf(x2, q, 4.89352518554385e-03f);
    float t = p / q;  // exact IEEE division, matching XLA's fdiv
    return (fabsf(x) < 0.0004f) ? x : t;
}

__device__ __forceinline__ float sigmoid_xla(float x) {
    // XLA logistic expansion: 0.5 + 0.5 * tanh(0.5 x)
    return fmaf(0.5f, tanh_xla(0.5f * x), 0.5f);
}

// ---------------- w1eT[b][h][t] = sum_k enc[b][t][k] * W1[k][h] ----------------
// grid = B*8 blocks (64 t-rows each), 256 threads, dynamic smem (W1 full + enc tile)
__global__ void __launch_bounds__(256) w1e_kernel(const float* __restrict__ enc,
                                                  const float* __restrict__ W1) {
    extern __shared__ float smem[];
    float* sW1 = smem;               // 128*128 floats
    float* senc = smem + 128 * 128;  // 64 rows * 129 (padded)
    int tid = threadIdx.x;
    int b = blockIdx.x >> 3;
    int t0 = (blockIdx.x & 7) * 64;

    for (int i = tid; i < 128 * 128; i += 256) sW1[i] = W1[i];
    for (int i = tid; i < 64 * 128; i += 256) {
        int r = i >> 7, k = i & 127;
        senc[r * 129 + k] = enc[((size_t)b * T + t0 + r) * H + k];
    }
    __syncthreads();

    int t = tid & 63, hg = tid >> 6;  // thread: row t, 32 h-columns of group hg
    float acc[32];
#pragma unroll
    for (int i = 0; i < 32; i++) acc[i] = 0.0f;
#pragma unroll 4
    for (int k = 0; k < 128; k++) {
        float e = senc[t * 129 + k];
        const float4* w4 = (const float4*)(sW1 + k * 128 + hg * 32);
#pragma unroll
        for (int q = 0; q < 8; q++) {
            float4 w = w4[q];
            acc[q * 4 + 0] = fmaf(e, w.x, acc[q * 4 + 0]);
            acc[q * 4 + 1] = fmaf(e, w.y, acc[q * 4 + 1]);
            acc[q * 4 + 2] = fmaf(e, w.z, acc[q * 4 + 2]);
            acc[q * 4 + 3] = fmaf(e, w.w, acc[q * 4 + 3]);
        }
    }
    size_t base = (size_t)b * H * T + (size_t)t0 + t;
#pragma unroll
    for (int i = 0; i < 32; i++)
        g_w1eT[base + (size_t)(hg * 32 + i) * T] = acc[i];
}

// ---------------- persistent per-batch decoder: all 512 steps in one block ----------------
__global__ void __launch_bounds__(256) decoder_kernel(
    const float* __restrict__ x, const float* __restrict__ h0,
    const float* __restrict__ c0, const float* __restrict__ kern,
    const float* __restrict__ reck, const float* __restrict__ bias,
    const float* __restrict__ W2, const float* __restrict__ V,
    float* __restrict__ out) {
    __shared__ float sh[H];       // hidden state
    __shared__ float su[H];       // h2 @ W2
    __shared__ float sV[H];
    __shared__ float sz[G4];      // LSTM pre-activations
    __shared__ float sK0[G4], sK1[G4], sb[G4];
    __shared__ float sx[T * 2];   // this batch's x rows
    __shared__ float sptr[2];
    __shared__ float rv[8];
    __shared__ int ri[8];

    int tid = threadIdx.x;
    int b = blockIdx.x;
    int lane = tid & 31, wid = tid >> 5;

    for (int i = tid; i < T * 2; i += 256) sx[i] = x[(size_t)b * T * 2 + i];
    for (int i = tid; i < G4; i += 256) {
        sK0[i] = kern[i];
        sK1[i] = kern[G4 + i];
        sb[i] = bias[i];
    }
    if (tid < H) { sh[tid] = h0[b * H + tid]; sV[tid] = V[tid]; }
    float creg = (tid < H) ? c0[b * H + tid] : 0.0f;
    if (tid == 0) { sptr[0] = 1.0f; sptr[1] = 1.0f; }
    __syncthreads();

    const float* wpb = g_w1eT + (size_t)b * H * T;
    const float2* R2 = (const float2*)reck;
    int r0 = tid, r1 = tid + 256;

    for (int s = 0; s < T; s++) {
        // ---- z = ptr@K + h@R + bias ; thread owns gate outputs j=2t, 2t+1 ----
        float p0 = sptr[0], p1 = sptr[1];
        int j0 = 2 * tid;
        float z0 = fmaf(p1, sK1[j0], fmaf(p0, sK0[j0], sb[j0]));
        float z1 = fmaf(p1, sK1[j0 + 1], fmaf(p0, sK0[j0 + 1], sb[j0 + 1]));
        {
            const float2* rp = R2 + tid;
#pragma unroll 4
            for (int h = 0; h < H; h++) {
                float hv = sh[h];
                float2 r = __ldg(rp);  // coalesced LDG.64
                rp += (G4 / 2);
                z0 = fmaf(hv, r.x, z0);
                z1 = fmaf(hv, r.y, z1);
            }
        }
        sz[j0] = z0;
        sz[j0 + 1] = z1;
        __syncthreads();

        // ---- gates (threads 0..127 own cell tid) ----
        if (tid < H) {
            float ig = sigmoid_xla(sz[tid]);
            float fg = sigmoid_xla(sz[tid + H]);
            float gg = tanh_xla(sz[tid + 2 * H]);
            float og = sigmoid_xla(sz[tid + 3 * H]);
            float c2 = fg * creg + ig * gg;
            creg = c2;
            sh[tid] = og * tanh_xla(c2);
        }
        __syncthreads();

        // ---- u = h2 @ W2 ----
        if (tid < H) {
            float u = 0.0f;
            const float* w2p = W2 + tid;
#pragma unroll 4
            for (int h = 0; h < H; h++) {
                u = fmaf(sh[h], __ldg(w2p), u);
                w2p += H;
            }
            su[tid] = u;
        }
        __syncthreads();

        // ---- scores: acc_t' = sum_h V[h] * tanh(w1eT[h][t'] + u[h]) ----
        float acc0 = 0.0f, acc1 = 0.0f;
        {
            const float* wp0 = wpb + r0;
            const float* wp1 = wpb + r1;
            const float4* u4p = (const float4*)su;
            const float4* v4p = (const float4*)sV;
#pragma unroll 4
            for (int q = 0; q < H / 4; q++) {
                float4 u4 = u4p[q];
                float4 v4 = v4p[q];
                float a0, a1;
                a0 = wp0[0]; a1 = wp1[0];
                acc0 = fmaf(v4.x, tanh_xla(a0 + u4.x), acc0);
                acc1 = fmaf(v4.x, tanh_xla(a1 + u4.x), acc1);
                a0 = wp0[T]; a1 = wp1[T];
                acc0 = fmaf(v4.y, tanh_xla(a0 + u4.y), acc0);
                acc1 = fmaf(v4.y, tanh_xla(a1 + u4.y), acc1);
                a0 = wp0[2 * T]; a1 = wp1[2 * T];
                acc0 = fmaf(v4.z, tanh_xla(a0 + u4.z), acc0);
                acc1 = fmaf(v4.z, tanh_xla(a1 + u4.z), acc1);
                a0 = wp0[3 * T]; a1 = wp1[3 * T];
                acc0 = fmaf(v4.w, tanh_xla(a0 + u4.w), acc0);
                acc1 = fmaf(v4.w, tanh_xla(a1 + u4.w), acc1);
                wp0 += 4 * T;
                wp1 += 4 * T;
            }
        }
        size_t ob = ((size_t)b * T + s) * T;
        out[ob + r0] = acc0;
        out[ob + r1] = acc1;

        // ---- argmax over t' (tie -> lowest index) + pointer select ----
        float best;
        int bidx;
        if (acc1 > acc0) { best = acc1; bidx = r1; }
        else             { best = acc0; bidx = r0; }
#pragma unroll
        for (int o = 16; o > 0; o >>= 1) {
            float ov = __shfl_xor_sync(0xffffffffu, best, o);
            int oi = __shfl_xor_sync(0xffffffffu, bidx, o);
            if (ov > best || (ov == best && oi < bidx)) { best = ov; bidx = oi; }
        }
        if (lane == 0) { rv[wid] = best; ri[wid] = bidx; }
        __syncthreads();
        if (tid == 0) {
            float bb = rv[0];
            int bi = ri[0];
#pragma unroll
            for (int w = 1; w < 8; w++)
                if (rv[w] > bb || (rv[w] == bb && ri[w] < bi)) { bb = rv[w]; bi = ri[w]; }
            sptr[0] = sx[bi * 2];
            sptr[1] = sx[bi * 2 + 1];
        }
        __syncthreads();
    }
}

// ---------------- launch: only 2 graph nodes ----------------
extern "C" void kernel_launch(void* const* d_in, const int* in_sizes, int n_in,
                              void* d_out, int out_size) {
    const float* x = (const float*)d_in[0];
    const float* enc = (const float*)d_in[1];
    const float* h0 = (const float*)d_in[2];
    const float* c0 = (const float*)d_in[3];
    const float* kern = (const float*)d_in[4];
    const float* reck = (const float*)d_in[5];
    const float* bias = (const float*)d_in[6];
    const float* W1 = (const float*)d_in[7];
    const float* W2 = (const float*)d_in[8];
    const float* V = (const float*)d_in[9];
    float* out = (float*)d_out;

    const int smem_w1e = (128 * 128 + 64 * 129) * 4;  // 98560 B
    cudaFuncSetAttribute(w1e_kernel, cudaFuncAttributeMaxDynamicSharedMemorySize, smem_w1e);
    w1e_kernel<<<B * 8, 256, smem_w1e>>>(enc, W1);
    decoder_kernel<<<B, 256>>>(x, h0, c0, kern, reck, bias, W2, V, out);
}

// round 5
// speedup vs baseline: 2.1692x; 2.1692x over previous
#include <cuda_runtime.h>

#define B 512
#define T 512
#define H 128
#define G4 (4 * H)  // 512

// w1e stored TRANSPOSED: [b][h][t'] -> coalesced loads in the hot loop
__device__ float g_w1eT[(size_t)B * H * T];

// ---------------- tanh: XLA rational coefficients, rcp+Newton division ----------------
__device__ __forceinline__ float tanh_fast(float x) {
    float xc = fminf(fmaxf(x, -9.0f), 9.0f);
    float x2 = xc * xc;
    float p = fmaf(x2, -2.76076847742355e-16f, 2.00018790482477e-13f);
    p = fmaf(x2, p, -8.60467152213735e-11f);
    p = fmaf(x2, p, 5.12229709037114e-08f);
    p = fmaf(x2, p, 1.48572235717979e-05f);
    p = fmaf(x2, p, 6.37261928875436e-04f);
    p = fmaf(x2, p, 4.89352455891786e-03f);
    p = xc * p;
    float q = fmaf(x2, 1.19825839466702e-06f, 1.18534705686654e-04f);
    q = fmaf(x2, q, 2.26843463243900e-03f);
    q = fmaf(x2, q, 4.89352518554385e-03f);
    float r;
    asm("rcp.approx.f32 %0, %1;" : "=f"(r) : "f"(q));
    r = r * fmaf(-q, r, 2.0f);  // one Newton step -> ~1 ulp
    return p * r;
}

__device__ __forceinline__ float sigmoid_fast(float x) {
    return fmaf(0.5f, tanh_fast(0.5f * x), 0.5f);
}

// ---------------- w1eT[b][h][t] = sum_k enc[b][t][k] * W1[k][h] ----------------
__global__ void __launch_bounds__(256) w1e_kernel(const float* __restrict__ enc,
                                                  const float* __restrict__ W1) {
    extern __shared__ float smem[];
    float* sW1 = smem;               // 128*128
    float* senc = smem + 128 * 128;  // 64 * 129 padded
    int tid = threadIdx.x;
    int b = blockIdx.x >> 3;
    int t0 = (blockIdx.x & 7) * 64;

    for (int i = tid; i < 128 * 128; i += 256) sW1[i] = W1[i];
    for (int i = tid; i < 64 * 128; i += 256) {
        int r = i >> 7, k = i & 127;
        senc[r * 129 + k] = enc[((size_t)b * T + t0 + r) * H + k];
    }
    __syncthreads();

    int t = tid & 63, hg = tid >> 6;
    float acc[32];
#pragma unroll
    for (int i = 0; i < 32; i++) acc[i] = 0.0f;
#pragma unroll 4
    for (int k = 0; k < 128; k++) {
        float e = senc[t * 129 + k];
        const float4* w4 = (const float4*)(sW1 + k * 128 + hg * 32);
#pragma unroll
        for (int q = 0; q < 8; q++) {
            float4 w = w4[q];
            acc[q * 4 + 0] = fmaf(e, w.x, acc[q * 4 + 0]);
            acc[q * 4 + 1] = fmaf(e, w.y, acc[q * 4 + 1]);
            acc[q * 4 + 2] = fmaf(e, w.z, acc[q * 4 + 2]);
            acc[q * 4 + 3] = fmaf(e, w.w, acc[q * 4 + 3]);
        }
    }
    size_t base = (size_t)b * H * T + (size_t)t0 + t;
#pragma unroll
    for (int i = 0; i < 32; i++)
        g_w1eT[base + (size_t)(hg * 32 + i) * T] = acc[i];
}

// ---------------- persistent per-batch decoder: 512 threads, 1 t' per thread ----------------
__global__ void __launch_bounds__(512, 3) decoder_kernel(
    const float* __restrict__ x, const float* __restrict__ h0,
    const float* __restrict__ c0, const float* __restrict__ kern,
    const float* __restrict__ reck, const float* __restrict__ bias,
    const float* __restrict__ W2, const float* __restrict__ V,
    float* __restrict__ out) {
    __shared__ float sh[H];
    __shared__ float su[H];
    __shared__ float sV[H];
    __shared__ float sz[G4];
    __shared__ float sK0[G4], sK1[G4], sb[G4];
    __shared__ float sx[T * 2];
    __shared__ float sptr[2];
    __shared__ float rv[16];
    __shared__ int ri[16];

    int tid = threadIdx.x;
    int b = blockIdx.x;
    int lane = tid & 31, wid = tid >> 5;

    for (int i = tid; i < T * 2; i += 512) sx[i] = x[(size_t)b * T * 2 + i];
    for (int i = tid; i < G4; i += 512) {
        sK0[i] = kern[i];
        sK1[i] = kern[G4 + i];
        sb[i] = bias[i];
    }
    if (tid < H) { sh[tid] = h0[b * H + tid]; sV[tid] = V[tid]; }
    float creg = (tid < H) ? c0[b * H + tid] : 0.0f;
    if (tid == 0) { sptr[0] = 1.0f; sptr[1] = 1.0f; }
    __syncthreads();

    const float* wpb = g_w1eT + (size_t)b * H * T;

    for (int s = 0; s < T; s++) {
        // ---- A: z_j = bias + ptr@K + h@R, one gate output per thread ----
        {
            float p0 = sptr[0], p1 = sptr[1];
            float z = fmaf(p1, sK1[tid], fmaf(p0, sK0[tid], sb[tid]));
            const float* rp = reck + tid;
#pragma unroll 8
            for (int h = 0; h < H; h++)
                z = fmaf(sh[h], __ldg(rp + (size_t)h * G4), z);
            sz[tid] = z;
        }
        __syncthreads();

        // ---- B: gates (threads 0..127) ----
        if (tid < H) {
            float ig = sigmoid_fast(sz[tid]);
            float fg = sigmoid_fast(sz[tid + H]);
            float gg = tanh_fast(sz[tid + 2 * H]);
            float og = sigmoid_fast(sz[tid + 3 * H]);
            float c2 = fg * creg + ig * gg;
            creg = c2;
            sh[tid] = og * tanh_fast(c2);
        }
        __syncthreads();

        // ---- C: u = h2 @ W2 (threads 0..127) ----
        if (tid < H) {
            float u = 0.0f;
            const float* w2p = W2 + tid;
#pragma unroll 8
            for (int h = 0; h < H; h++) u = fmaf(sh[h], __ldg(w2p + h * H), u);
            su[tid] = u;
        }
        __syncthreads();

        // ---- D: score(t'=tid) = sum_h V[h] * tanh(w1eT[h][t'] + u[h]) ----
        float acc0 = 0.0f, acc1 = 0.0f;
        {
            const float* wp = wpb + tid;
            const float4* u4p = (const float4*)su;
            const float4* v4p = (const float4*)sV;
#pragma unroll 4
            for (int q = 0; q < H / 4; q++) {
                float4 u4 = u4p[q];
                float4 v4 = v4p[q];
                float a0 = wp[0];
                float a1 = wp[T];
                float a2 = wp[2 * T];
                float a3 = wp[3 * T];
                acc0 = fmaf(v4.x, tanh_fast(a0 + u4.x), acc0);
                acc1 = fmaf(v4.y, tanh_fast(a1 + u4.y), acc1);
                acc0 = fmaf(v4.z, tanh_fast(a2 + u4.z), acc0);
                acc1 = fmaf(v4.w, tanh_fast(a3 + u4.w), acc1);
                wp += 4 * T;
            }
        }
        float acc = acc0 + acc1;
        out[((size_t)b * T + s) * T + tid] = acc;

        // ---- argmax (tie -> lowest index) ----
        float best = acc;
        int bidx = tid;
#pragma unroll
        for (int o = 16; o > 0; o >>= 1) {
            float ov = __shfl_xor_sync(0xffffffffu, best, o);
            int oi = __shfl_xor_sync(0xffffffffu, bidx, o);
            if (ov > best || (ov == best && oi < bidx)) { best = ov; bidx = oi; }
        }
        if (lane == 0) { rv[wid] = best; ri[wid] = bidx; }
        __syncthreads();
        if (wid == 0) {
            float bb = (lane < 16) ? rv[lane] : rv[0];
            int bi = (lane < 16) ? ri[lane] : ri[0];
#pragma unroll
            for (int o = 8; o > 0; o >>= 1) {
                float ov = __shfl_xor_sync(0xffffffffu, bb, o);
                int oi = __shfl_xor_sync(0xffffffffu, bi, o);
                if (ov > bb || (ov == bb && oi < bi)) { bb = ov; bi = oi; }
            }
            if (lane == 0) {
                sptr[0] = sx[bi * 2];
                sptr[1] = sx[bi * 2 + 1];
            }
        }
        __syncthreads();
    }
}

// ---------------- launch: 2 graph nodes ----------------
extern "C" void kernel_launch(void* const* d_in, const int* in_sizes, int n_in,
                              void* d_out, int out_size) {
    const float* x = (const float*)d_in[0];
    const float* enc = (const float*)d_in[1];
    const float* h0 = (const float*)d_in[2];
    const float* c0 = (const float*)d_in[3];
    const float* kern = (const float*)d_in[4];
    const float* reck = (const float*)d_in[5];
    const float* bias = (const float*)d_in[6];
    const float* W1 = (const float*)d_in[7];
    const float* W2 = (const float*)d_in[8];
    const float* V = (const float*)d_in[9];
    float* out = (float*)d_out;

    const int smem_w1e = (128 * 128 + 64 * 129) * 4;  // 98560 B
    cudaFuncSetAttribute(w1e_kernel, cudaFuncAttributeMaxDynamicSharedMemorySize, smem_w1e);
    w1e_kernel<<<B * 8, 256, smem_w1e>>>(enc, W1);
    decoder_kernel<<<B, 512>>>(x, h0, c0, kern, reck, bias, W2, V, out);
}